// round 8
// baseline (speedup 1.0000x reference)
#include <cuda_runtime.h>
#include <math.h>

#define N_NODES 50000
#define N_EDGES 800000
#define DIM     128
#define NQ      8
#define QDIM    768
#define NREL    50
#define NB      8
#define NLAYERS 3

// ---------------- scratch (device globals; no allocs allowed) ----------------
__device__ float g_ha[N_NODES * DIM];    // node features (ping)
__device__ float g_hb[N_NODES * DIM];    // node features (pong)
__device__ float g_agg[N_NODES * DIM];   // per-node message accumulator
__device__ float g_W[NREL * DIM * DIM];  // per-relation composed weights
__device__ float g_q[NQ * DIM];
__device__ float g_att[N_EDGES];
__device__ int   g_deg[N_NODES];
__device__ float g_dinv[N_NODES];

// ---------------- degree init ----------------
__global__ void k_degclr() {
    int v = blockIdx.x * blockDim.x + threadIdx.x;
    if (v < N_NODES) g_deg[v] = 0;
}

__global__ void k_deghist(const int* dst) {
    int e = blockIdx.x * blockDim.x + threadIdx.x;
    if (e < N_EDGES) atomicAdd(&g_deg[dst[e]], 1);
}

__global__ void k_deginv() {
    int v = blockIdx.x * blockDim.x + threadIdx.x;
    if (v < N_NODES) {
        int d = g_deg[v];
        if (d < 1) d = 1;
        g_dinv[v] = __fdividef(1.0f, (float)d);
    }
}

// ---------------- query projection: g_q[qi][j] ----------------
__global__ void k_qproj(const float* qe, const float* w, const float* b) {
    int qi = blockIdx.x;
    int j = threadIdx.x;
    float acc = b[j];
    for (int k = 0; k < QDIM; k++) acc += qe[qi * QDIM + k] * w[k * DIM + j];
    g_q[qi * DIM + j] = acc;
}

// ---------------- input transform: g_ha[v][j] = embed[x[v]] @ ilw + ilb ----------------
__global__ void k_hinit(const int* x, const float* ew, const float* ilw, const float* ilb) {
    int idx = blockIdx.x * blockDim.x + threadIdx.x;
    if (idx >= N_NODES * DIM) return;
    int v = idx >> 7;
    int j = idx & 127;
    int xv = x[v];
    float acc = ilb[j];
    for (int k = 0; k < DIM; k++) acc += ew[xv * DIM + k] * ilw[k * DIM + j];
    g_ha[idx] = acc;
}

// ---------------- per-relation composed weight ----------------
__global__ void k_relW(const float* bases_l, const float* comp_l) {
    int r = blockIdx.x;
    float c0 = comp_l[r * NB + 0], c1 = comp_l[r * NB + 1];
    float c2 = comp_l[r * NB + 2], c3 = comp_l[r * NB + 3];
    float c4 = comp_l[r * NB + 4], c5 = comp_l[r * NB + 5];
    float c6 = comp_l[r * NB + 6], c7 = comp_l[r * NB + 7];
    for (int idx = threadIdx.x; idx < DIM * DIM; idx += blockDim.x) {
        float s0 = c0 * bases_l[0 * DIM * DIM + idx]
                 + c1 * bases_l[1 * DIM * DIM + idx]
                 + c2 * bases_l[2 * DIM * DIM + idx]
                 + c3 * bases_l[3 * DIM * DIM + idx]
                 + c4 * bases_l[4 * DIM * DIM + idx]
                 + c5 * bases_l[5 * DIM * DIM + idx]
                 + c6 * bases_l[6 * DIM * DIM + idx]
                 + c7 * bases_l[7 * DIM * DIM + idx];
        g_W[r * DIM * DIM + idx] = s0;
    }
}

// ---------------- per-edge attention ----------------
__global__ void k_att(const float* attn_l, const int* ebatch, const int* etype) {
    int e = blockIdx.x * blockDim.x + threadIdx.x;
    if (e >= N_EDGES) return;
    int qb = ebatch[e] * DIM;
    int ab = etype[e] * DIM;
    float s = 0.f;
    for (int i = 0; i < DIM; i++) s += g_q[qb + i] * attn_l[ab + i];
    float ex = __expf(-s);
    g_att[e] = __fdividef(1.0f, 1.0f + ex);
}

// ---------------- clear aggregation buffer ----------------
__global__ void k_aggclr() {
    int idx = blockIdx.x * blockDim.x + threadIdx.x;
    if (idx < N_NODES * DIM) g_agg[idx] = 0.f;
}

// ---------------- edge messages: atomicAdd(agg[dst][j], att*(h[src] @ W[rel])[j]) ----------------
// block = 256 threads = 2 edges x 128 cols
__global__ void k_msg(const float* h, const int* src, const int* dst, const int* etype) {
    int tid = threadIdx.x;
    int j = tid & 127;
    int e = blockIdx.x * 2 + (tid >> 7);
    if (e >= N_EDGES) return;
    int s = src[e];
    int r = etype[e];
    float acc = 0.f;
    const float* hp = h + s * DIM;
    const float* wp = g_W + r * DIM * DIM + j;
    for (int k = 0; k < DIM; k++) acc += hp[k] * wp[k * DIM];
    atomicAdd(&g_agg[dst[e] * DIM + j], g_att[e] * acc);
}

// ---------------- output: dest[v][j] = agg[v][j]*dinv[v] + (h[v] @ root)[j] + bias[j] ----------------
__global__ void k_out(const float* h, const float* rootw, const float* lbias,
                      float* dest, int do_relu) {
    int idx = blockIdx.x * blockDim.x + threadIdx.x;
    if (idx >= N_NODES * DIM) return;
    int v = idx >> 7;
    int j = idx & 127;
    float acc = lbias[j];
    const float* hp = h + v * DIM;
    const float* wp = rootw + j;
    for (int k = 0; k < DIM; k++) acc += hp[k] * wp[k * DIM];
    float o = acc + g_agg[idx] * g_dinv[v];
    if (do_relu && o < 0.f) o = 0.f;
    dest[idx] = o;
}

// ---------------- launch ----------------
extern "C" void kernel_launch(void* const* d_in, const int* in_sizes, int n_in,
                              void* d_out, int out_size) {
    const int*   x          = (const int*)d_in[0];
    const int*   edge_index = (const int*)d_in[1];
    const int*   edge_type  = (const int*)d_in[2];
    const float* query_emb  = (const float*)d_in[3];
    // d_in[4] = x_batch (unused by reference)
    const int*   edge_batch = (const int*)d_in[5];
    const float* embed_w    = (const float*)d_in[6];
    const float* ilw        = (const float*)d_in[7];
    const float* ilb        = (const float*)d_in[8];
    const float* qpw        = (const float*)d_in[9];
    const float* qpb        = (const float*)d_in[10];
    const float* bases      = (const float*)d_in[11];
    const float* comp       = (const float*)d_in[12];
    const float* rootw      = (const float*)d_in[13];
    const float* lbias      = (const float*)d_in[14];
    const float* relattn    = (const float*)d_in[15];
    float* out = (float*)d_out;

    const int* src = edge_index;
    const int* dst = edge_index + N_EDGES;

    const int NODEB = (N_NODES + 255) / 256;
    const int NDB   = (N_NODES * DIM + 255) / 256;
    const int EBLK  = (N_EDGES + 255) / 256;
    const int MSGB  = (N_EDGES + 1) / 2;

    // resolve device-global addresses host-side for ping-pong
    float* ha = nullptr; float* hb = nullptr;
    cudaGetSymbolAddress((void**)&ha, g_ha);
    cudaGetSymbolAddress((void**)&hb, g_hb);

    k_qproj<<<NQ, DIM>>>(query_emb, qpw, qpb);
    k_hinit<<<NDB, 256>>>(x, embed_w, ilw, ilb);
    k_degclr<<<NODEB, 256>>>();
    k_deghist<<<EBLK, 256>>>(dst);
    k_deginv<<<NODEB, 256>>>();

    float* cur = ha;
    float* nxt = hb;
    for (int l = 0; l < NLAYERS; l++) {
        k_relW<<<NREL, 256>>>(bases + (size_t)l * NB * DIM * DIM,
                              comp + (size_t)l * NREL * NB);
        k_att<<<EBLK, 256>>>(relattn + (size_t)l * NREL * DIM, edge_batch, edge_type);
        k_aggclr<<<NDB, 256>>>();
        k_msg<<<MSGB, 256>>>(cur, src, dst, edge_type);
        float* dest = (l == NLAYERS - 1) ? out : nxt;
        k_out<<<NDB, 256>>>(cur, rootw + (size_t)l * DIM * DIM,
                            lbias + (size_t)l * DIM, dest, (l < NLAYERS - 1) ? 1 : 0);
        float* t = cur; cur = nxt; nxt = t;
    }
}

// round 9
// speedup vs baseline: 2.2263x; 2.2263x over previous
#include <cuda_runtime.h>
#include <math.h>

#define N_NODES 50000
#define N_EDGES 800000
#define DIM     128
#define NQ      8
#define QDIM    768
#define NREL    50
#define NB      8
#define NLAYERS 3
#define ET      64                         // edges per tile
#define KC      32                         // k-chunk
#define NCHUNK  (DIM / KC)
#define ATS     (ET + 1)                   // padded row stride for Ats
#define PERM_SZ (N_EDGES + NREL * ET)

// ---------------- scratch (device globals; no allocs allowed) ----------------
__device__ float g_ha[N_NODES * DIM];    // node features (ping)
__device__ float g_hb[N_NODES * DIM];    // node features (pong)
__device__ float g_agg[N_NODES * DIM];   // per-node message accumulator
__device__ float g_W[NREL * DIM * DIM];  // per-relation composed weights
__device__ float g_q[NQ * DIM];
__device__ float g_att[N_EDGES];
__device__ int   g_deg[N_NODES];
__device__ float g_dinv[N_NODES];
__device__ int   g_relhist[NREL];
__device__ int   g_pstart[NREL + 1];
__device__ int   g_relcur[NREL];
__device__ int   g_perm[PERM_SZ];

// ---------------- init ----------------
__global__ void k_degclr() {
    int v = blockIdx.x * blockDim.x + threadIdx.x;
    if (v < N_NODES) g_deg[v] = 0;
}

__global__ void k_permclr() {
    int i = blockIdx.x * blockDim.x + threadIdx.x;
    if (i < PERM_SZ) g_perm[i] = -1;
    if (i < NREL) { g_relhist[i] = 0; g_relcur[i] = 0; }
}

__global__ void k_deghist(const int* dst) {
    int e = blockIdx.x * blockDim.x + threadIdx.x;
    if (e < N_EDGES) atomicAdd(&g_deg[dst[e]], 1);
}

__global__ void k_relhist(const int* etype) {
    int e = blockIdx.x * blockDim.x + threadIdx.x;
    if (e < N_EDGES) atomicAdd(&g_relhist[etype[e]], 1);
}

__global__ void k_reloff() {
    if (blockIdx.x == 0 && threadIdx.x == 0) {
        int run = 0;
        for (int r = 0; r < NREL; r++) {
            g_pstart[r] = run;
            run += ((g_relhist[r] + ET - 1) / ET) * ET;
        }
        g_pstart[NREL] = run;
    }
}

__global__ void k_scatter_rel(const int* etype) {
    int e = blockIdx.x * blockDim.x + threadIdx.x;
    if (e < N_EDGES) {
        int r = etype[e];
        int pos = g_pstart[r] + atomicAdd(&g_relcur[r], 1);
        g_perm[pos] = e;
    }
}

__global__ void k_deginv() {
    int v = blockIdx.x * blockDim.x + threadIdx.x;
    if (v < N_NODES) {
        int d = g_deg[v];
        if (d < 1) d = 1;
        g_dinv[v] = __fdividef(1.0f, (float)d);
    }
}

// ---------------- query projection ----------------
__global__ void k_qproj(const float* qe, const float* w, const float* b) {
    int qi = blockIdx.x;
    int j = threadIdx.x;
    float acc = b[j];
    for (int k = 0; k < QDIM; k++) acc += qe[qi * QDIM + k] * w[k * DIM + j];
    g_q[qi * DIM + j] = acc;
}

// ---------------- input transform ----------------
__global__ void k_hinit(const int* x, const float* ew, const float* ilw, const float* ilb) {
    int idx = blockIdx.x * blockDim.x + threadIdx.x;
    if (idx >= N_NODES * DIM) return;
    int v = idx >> 7;
    int j = idx & 127;
    int xv = x[v];
    float acc = ilb[j];
    for (int k = 0; k < DIM; k++) acc += ew[xv * DIM + k] * ilw[k * DIM + j];
    g_ha[idx] = acc;
}

// ---------------- per-relation composed weight ----------------
__global__ void k_relW(const float* bases_l, const float* comp_l) {
    int r = blockIdx.x;
    float c0 = comp_l[r * NB + 0], c1 = comp_l[r * NB + 1];
    float c2 = comp_l[r * NB + 2], c3 = comp_l[r * NB + 3];
    float c4 = comp_l[r * NB + 4], c5 = comp_l[r * NB + 5];
    float c6 = comp_l[r * NB + 6], c7 = comp_l[r * NB + 7];
    for (int idx = threadIdx.x; idx < DIM * DIM; idx += blockDim.x) {
        float s0 = c0 * bases_l[0 * DIM * DIM + idx]
                 + c1 * bases_l[1 * DIM * DIM + idx]
                 + c2 * bases_l[2 * DIM * DIM + idx]
                 + c3 * bases_l[3 * DIM * DIM + idx]
                 + c4 * bases_l[4 * DIM * DIM + idx]
                 + c5 * bases_l[5 * DIM * DIM + idx]
                 + c6 * bases_l[6 * DIM * DIM + idx]
                 + c7 * bases_l[7 * DIM * DIM + idx];
        g_W[r * DIM * DIM + idx] = s0;
    }
}

// ---------------- per-edge attention ----------------
__global__ void k_att(const float* attn_l, const int* ebatch, const int* etype) {
    int e = blockIdx.x * blockDim.x + threadIdx.x;
    if (e >= N_EDGES) return;
    int qb = ebatch[e] * DIM;
    int ab = etype[e] * DIM;
    float s = 0.f;
    for (int i = 0; i < DIM; i++) s += g_q[qb + i] * attn_l[ab + i];
    float ex = __expf(-s);
    g_att[e] = __fdividef(1.0f, 1.0f + ex);
}

// ---------------- clear aggregation buffer ----------------
__global__ void k_aggclr() {
    int idx = blockIdx.x * blockDim.x + threadIdx.x;
    if (idx < N_NODES * DIM) g_agg[idx] = 0.f;
}

// ---------------- tiled edge messages (relation-sorted) ----------------
// 64 edges x 128 cols per 256-thread block; thread = 4 rows x 8 cols.
// M[e][j] = att_e * sum_k h[src_e][k] * W[rel][k][j]; atomicAdd into g_agg[dst_e].
#define ROWFMA(m) \
    c##m##0 += a##m * b0; c##m##1 += a##m * b1; c##m##2 += a##m * b2; c##m##3 += a##m * b3; \
    c##m##4 += a##m * b4; c##m##5 += a##m * b5; c##m##6 += a##m * b6; c##m##7 += a##m * b7;

#define ROWOUT(m) \
    { int e = s_eid[4 * rg + m]; \
      if (e >= 0) { \
          float* gp = g_agg + s_dst[4 * rg + m] * DIM + cg; \
          atomicAdd(gp +   0, c##m##0); atomicAdd(gp +  16, c##m##1); \
          atomicAdd(gp +  32, c##m##2); atomicAdd(gp +  48, c##m##3); \
          atomicAdd(gp +  64, c##m##4); atomicAdd(gp +  80, c##m##5); \
          atomicAdd(gp +  96, c##m##6); atomicAdd(gp + 112, c##m##7); } }

__global__ void k_emsg(const float* h, const int* src, const int* dst) {
    __shared__ float Bs[KC * DIM];      // 16 KB W chunk
    __shared__ float Ats[KC * ATS];     // 8.1 KB transposed, att-scaled h chunk
    __shared__ int   s_eid[ET];
    __shared__ int   s_src[ET];
    __shared__ int   s_dst[ET];
    __shared__ float s_att[ET];
    __shared__ int   s_rel;

    int tid = threadIdx.x;
    int tilebase = blockIdx.x * ET;

    if (tid == 0) {
        int r = 0;
        while (r < NREL && !(tilebase >= g_pstart[r] && tilebase < g_pstart[r + 1])) r++;
        s_rel = r;
    }
    if (tid < ET) {
        int e = g_perm[tilebase + tid];
        s_eid[tid] = e;
        s_src[tid] = (e >= 0) ? src[e] : 0;
        s_dst[tid] = (e >= 0) ? dst[e] : 0;
        s_att[tid] = (e >= 0) ? g_att[e] : 0.f;
    }
    __syncthreads();
    if (s_rel >= NREL) return;

    const float* Bg = g_W + s_rel * DIM * DIM;

    int cg = tid & 15;      // col group: cols cg + 16*i
    int rg = tid >> 4;      // row group: rows 4*rg + m
    float c00=0.f,c01=0.f,c02=0.f,c03=0.f,c04=0.f,c05=0.f,c06=0.f,c07=0.f;
    float c10=0.f,c11=0.f,c12=0.f,c13=0.f,c14=0.f,c15=0.f,c16=0.f,c17=0.f;
    float c20=0.f,c21=0.f,c22=0.f,c23=0.f,c24=0.f,c25=0.f,c26=0.f,c27=0.f;
    float c30=0.f,c31=0.f,c32=0.f,c33=0.f,c34=0.f,c35=0.f,c36=0.f,c37=0.f;

    int kA = tid & 31;          // k within chunk for A staging
    int rbase = (tid >> 5) * 8; // 8 rows per staging thread-group

    for (int kc = 0; kc < NCHUNK; kc++) {
        for (int i = 0; i < 16; i++) {
            int idx = i * 256 + tid;                  // 0..4095
            Bs[idx] = Bg[kc * KC * DIM + idx];
        }
        for (int i = 0; i < 8; i++) {
            int row = rbase + i;
            Ats[kA * ATS + row] =
                h[s_src[row] * DIM + kc * KC + kA] * s_att[row];
        }
        __syncthreads();

        for (int k = 0; k < KC; k++) {
            float a0 = Ats[k * ATS + 4 * rg + 0];
            float a1 = Ats[k * ATS + 4 * rg + 1];
            float a2 = Ats[k * ATS + 4 * rg + 2];
            float a3 = Ats[k * ATS + 4 * rg + 3];
            float b0 = Bs[k * DIM + cg + 0];
            float b1 = Bs[k * DIM + cg + 16];
            float b2 = Bs[k * DIM + cg + 32];
            float b3 = Bs[k * DIM + cg + 48];
            float b4 = Bs[k * DIM + cg + 64];
            float b5 = Bs[k * DIM + cg + 80];
            float b6 = Bs[k * DIM + cg + 96];
            float b7 = Bs[k * DIM + cg + 112];
            ROWFMA(0) ROWFMA(1) ROWFMA(2) ROWFMA(3)
        }
        __syncthreads();
    }

    ROWOUT(0) ROWOUT(1) ROWOUT(2) ROWOUT(3)
}

// ---------------- output: dest[v][j] = agg[v][j]*dinv[v] + (h[v] @ root)[j] + bias[j] ----------------
__global__ void k_out(const float* h, const float* rootw, const float* lbias,
                      float* dest, int do_relu) {
    int idx = blockIdx.x * blockDim.x + threadIdx.x;
    if (idx >= N_NODES * DIM) return;
    int v = idx >> 7;
    int j = idx & 127;
    float acc = lbias[j];
    const float* hp = h + v * DIM;
    const float* wp = rootw + j;
    for (int k = 0; k < DIM; k++) acc += hp[k] * wp[k * DIM];
    float o = acc + g_agg[idx] * g_dinv[v];
    if (do_relu && o < 0.f) o = 0.f;
    dest[idx] = o;
}

// ---------------- launch ----------------
extern "C" void kernel_launch(void* const* d_in, const int* in_sizes, int n_in,
                              void* d_out, int out_size) {
    const int*   x          = (const int*)d_in[0];
    const int*   edge_index = (const int*)d_in[1];
    const int*   edge_type  = (const int*)d_in[2];
    const float* query_emb  = (const float*)d_in[3];
    // d_in[4] = x_batch (unused by reference)
    const int*   edge_batch = (const int*)d_in[5];
    const float* embed_w    = (const float*)d_in[6];
    const float* ilw        = (const float*)d_in[7];
    const float* ilb        = (const float*)d_in[8];
    const float* qpw        = (const float*)d_in[9];
    const float* qpb        = (const float*)d_in[10];
    const float* bases      = (const float*)d_in[11];
    const float* comp       = (const float*)d_in[12];
    const float* rootw      = (const float*)d_in[13];
    const float* lbias      = (const float*)d_in[14];
    const float* relattn    = (const float*)d_in[15];
    float* out = (float*)d_out;

    const int* src = edge_index;
    const int* dst = edge_index + N_EDGES;

    const int NODEB = (N_NODES + 255) / 256;
    const int NDB   = (N_NODES * DIM + 255) / 256;
    const int EBLK  = (N_EDGES + 255) / 256;
    const int PBLK  = (PERM_SZ + 255) / 256;
    const int ETILES = PERM_SZ / ET;                  // 12550

    float* ha = nullptr; float* hb = nullptr;
    cudaGetSymbolAddress((void**)&ha, g_ha);
    cudaGetSymbolAddress((void**)&hb, g_hb);

    k_qproj<<<NQ, DIM>>>(query_emb, qpw, qpb);
    k_hinit<<<NDB, 256>>>(x, embed_w, ilw, ilb);
    k_degclr<<<NODEB, 256>>>();
    k_permclr<<<PBLK, 256>>>();
    k_deghist<<<EBLK, 256>>>(dst);
    k_relhist<<<EBLK, 256>>>(edge_type);
    k_reloff<<<1, 32>>>();
    k_scatter_rel<<<EBLK, 256>>>(edge_type);
    k_deginv<<<NODEB, 256>>>();

    float* cur = ha;
    float* nxt = hb;
    for (int l = 0; l < NLAYERS; l++) {
        k_relW<<<NREL, 256>>>(bases + (size_t)l * NB * DIM * DIM,
                              comp + (size_t)l * NREL * NB);
        k_att<<<EBLK, 256>>>(relattn + (size_t)l * NREL * DIM, edge_batch, edge_type);
        k_aggclr<<<NDB, 256>>>();
        k_emsg<<<ETILES, 256>>>(cur, src, dst);
        float* dest = (l == NLAYERS - 1) ? out : nxt;
        k_out<<<NDB, 256>>>(cur, rootw + (size_t)l * DIM * DIM,
                            lbias + (size_t)l * DIM, dest, (l < NLAYERS - 1) ? 1 : 0);
        float* t = cur; cur = nxt; nxt = t;
    }
}